// round 7
// baseline (speedup 1.0000x reference)
#include <cuda_runtime.h>

#define NN 64
#define CC 960
#define CS 240
#define HW 784
#define HW4 196      // float4s per (n,c) plane
#define NC (NN*CC)   // 61440 planes
#define NF4 12042240 // total float4s = NC*HW4
#define NBLK 47040   // NF4 / 256

// Scratch (no device allocs allowed).
__device__ float g_pooled[NC];
__device__ float g_hidden[NN*CS];

// ---------------------------------------------------------------------------
// Kernel 1: global average pool. One warp per TWO (n,c) planes.
// Doubles per-warp MLP and halves reduce/store epilogue per byte.
// ---------------------------------------------------------------------------
__global__ void pool_kernel(const float* __restrict__ x) {
    unsigned warp = (blockIdx.x * blockDim.x + threadIdx.x) >> 5;  // < NC/2
    unsigned lane = threadIdx.x & 31u;
    const float4* p = reinterpret_cast<const float4*>(x) + (size_t)warp * (2 * HW4);
    float s0 = 0.f, s1 = 0.f;
    #pragma unroll 7
    for (int i = lane; i < HW4; i += 32) {
        float4 a = p[i];
        float4 b = p[i + HW4];
        s0 += (a.x + a.y) + (a.z + a.w);
        s1 += (b.x + b.y) + (b.z + b.w);
    }
    #pragma unroll
    for (int o = 16; o; o >>= 1) {
        s0 += __shfl_xor_sync(0xffffffffu, s0, o);
        s1 += __shfl_xor_sync(0xffffffffu, s1, o);
    }
    if (lane == 0) {
        g_pooled[2 * warp]     = s0 * (1.0f / HW);
        g_pooled[2 * warp + 1] = s1 * (1.0f / HW);
    }
}

// ---------------------------------------------------------------------------
// Kernel 2: fc1 + relu. One warp per (n, o) output; 64*240 = 15360 warps.
// ---------------------------------------------------------------------------
__global__ void fc1_kernel(const float* __restrict__ w1, const float* __restrict__ b1) {
    unsigned w    = (blockIdx.x * blockDim.x + threadIdx.x) >> 5;   // < 15360
    unsigned lane = threadIdx.x & 31u;
    unsigned n = w / CS;
    unsigned o = w % CS;
    const float4* wr = reinterpret_cast<const float4*>(w1) + (size_t)o * (CC / 4);
    const float4* pr = reinterpret_cast<const float4*>(g_pooled) + (size_t)n * (CC / 4);
    float s = 0.f;
    #pragma unroll 8
    for (int i = lane; i < CC / 4; i += 32) {               // 240 float4s
        float4 a = wr[i], b = pr[i];
        s += a.x * b.x + a.y * b.y + a.z * b.z + a.w * b.w;
    }
    #pragma unroll
    for (int d = 16; d; d >>= 1) s += __shfl_xor_sync(0xffffffffu, s, d);
    if (lane == 0) g_hidden[n * CS + o] = fmaxf(s + b1[o], 0.f);
}

// ---------------------------------------------------------------------------
// Kernel 3: fused fc2 + hardsigmoid + broadcast multiply.
// Each block covers 256 consecutive float4s of x (≤3 planes). Warps 0..2
// compute the gate for those planes (redundantly across blocks — cheap,
// w2/g_hidden are L2-resident), then all 256 threads stream-multiply.
// Blocks are REVERSED so first-scheduled blocks read the tail of x, which
// is still L2-hot from pool_kernel (fc1 touches only ~2MB unique between).
// ---------------------------------------------------------------------------
__global__ void scale_fused_kernel(const float* __restrict__ x, float* __restrict__ out,
                                   const float* __restrict__ w2, const float* __restrict__ b2) {
    __shared__ float sc[3];
    unsigned blk  = (NBLK - 1u) - blockIdx.x;               // reversed order
    unsigned base = blk * 256u;                             // first float4 index
    unsigned nc0  = base / HW4;
    unsigned ncN  = (base + 255u) / HW4;                    // inclusive, ncN-nc0 <= 2
    unsigned wid  = threadIdx.x >> 5, lane = threadIdx.x & 31u;

    if (wid <= ncN - nc0) {
        unsigned nc = nc0 + wid;
        unsigned n = nc / CC, c = nc % CC;
        const float4* wr = reinterpret_cast<const float4*>(w2) + (size_t)c * (CS / 4);
        const float4* hr = reinterpret_cast<const float4*>(g_hidden) + (size_t)n * (CS / 4);
        float s = 0.f;
        #pragma unroll 2
        for (int i = lane; i < CS / 4; i += 32) {           // 60 float4s
            float4 a = wr[i], b = hr[i];
            s += a.x * b.x + a.y * b.y + a.z * b.z + a.w * b.w;
        }
        #pragma unroll
        for (int d = 16; d; d >>= 1) s += __shfl_xor_sync(0xffffffffu, s, d);
        if (lane == 0) sc[wid] = __saturatef((s + b2[c] + 3.f) * (1.f / 6.f));
    }
    __syncthreads();

    unsigned i  = base + threadIdx.x;
    unsigned nc = i / HW4;
    float s = sc[nc - nc0];
    float4 v = __ldcs(reinterpret_cast<const float4*>(x) + i);
    v.x *= s; v.y *= s; v.z *= s; v.w *= s;
    __stcs(reinterpret_cast<float4*>(out) + i, v);
}

// ---------------------------------------------------------------------------
extern "C" void kernel_launch(void* const* d_in, const int* in_sizes, int n_in,
                              void* d_out, int out_size) {
    const float* x  = (const float*)d_in[0];
    const float* w1 = (const float*)d_in[1];
    const float* b1 = (const float*)d_in[2];
    const float* w2 = (const float*)d_in[3];
    const float* b2 = (const float*)d_in[4];
    float* out = (float*)d_out;

    pool_kernel<<<(NC / 2 * 32) / 256, 256>>>(x);           // 3840 blocks
    fc1_kernel<<<(NN * CS * 32) / 256, 256>>>(w1, b1);      // 1920 blocks
    scale_fused_kernel<<<NBLK, 256>>>(x, out, w2, b2);      // 47040 blocks
}